// round 2
// baseline (speedup 1.0000x reference)
#include <cuda_runtime.h>
#include <cstdint>

// Problem constants
#define BATCH   8192
#define IN_DIM  768
#define LAT     16384
#define K_TOP   81          // max(1, int(8192*0.01))
#define ROW_CAP 1024
#define EQ_CAP  16

// ---------------- device scratch (allocation-free: module globals) ----------
__device__ float        g_dwt[(size_t)LAT * IN_DIM];      // dec_w transposed [LAT][IN_DIM]
__device__ unsigned int g_prefix[LAT];                    // radix-select prefix / final threshold bits
__device__ int          g_krem[LAT];                      // remaining rank within candidate class
__device__ int          g_eqcnt[LAT];
__device__ int          g_keepcnt[LAT];
__device__ int          g_eqrows[LAT * EQ_CAP];
__device__ int          g_rown[BATCH];
__device__ int          g_rcols[(size_t)BATCH * ROW_CAP];
__device__ float        g_rvals[(size_t)BATCH * ROW_CAP];

__device__ __forceinline__ unsigned int f2ord(float f) {
    unsigned int u = __float_as_uint(f);
    return u ^ ((u & 0x80000000u) ? 0xFFFFFFFFu : 0x80000000u);
}

// ---------------- init per-launch state (graph replays must be deterministic)
__global__ void k_init() {
    int i = blockIdx.x * blockDim.x + threadIdx.x;
    if (i < LAT) {
        g_prefix[i]  = 0u;
        g_krem[i]    = K_TOP;
        g_eqcnt[i]   = 0;
        g_keepcnt[i] = 0;
    }
    if (i < BATCH) g_rown[i] = 0;
}

// ---------------- transpose dec_w [IN_DIM][LAT] -> g_dwt [LAT][IN_DIM] ------
__global__ void k_transpose(const float* __restrict__ dw) {
    __shared__ float t[32][33];
    int bx = blockIdx.x * 32;   // LAT dim
    int by = blockIdx.y * 32;   // IN_DIM dim
    int x = bx + threadIdx.x;
    #pragma unroll
    for (int i = 0; i < 32; i += 8) {
        int y = by + threadIdx.y + i;
        t[threadIdx.y + i][threadIdx.x] = dw[(size_t)y * LAT + x];
    }
    __syncthreads();
    int xo = by + threadIdx.x;
    #pragma unroll
    for (int i = 0; i < 32; i += 8) {
        int yo = bx + threadIdx.y + i;
        g_dwt[(size_t)yo * IN_DIM + xo] = t[threadIdx.x][threadIdx.y + i];
    }
}

// ---------------- encoder SGEMM: C[B][LAT] = x[B][K] * enc_w[LAT][K]^T + b --
#define BM 128
#define BN 128
#define BKK 16

__global__ __launch_bounds__(256, 2)
void k_sgemm(const float* __restrict__ A, const float* __restrict__ B,
             const float* __restrict__ bias, float* __restrict__ C) {
    __shared__ float As[BKK][BM];
    __shared__ float Bs[BKK][BN];
    int tid = threadIdx.x;
    int bm = blockIdx.y * BM;
    int bn = blockIdx.x * BN;
    int txx = tid & 15;       // 0..15
    int tyy = tid >> 4;       // 0..15

    float acc[8][8];
    #pragma unroll
    for (int i = 0; i < 8; ++i)
        #pragma unroll
        for (int j = 0; j < 8; ++j) acc[i][j] = 0.0f;

    int lr = tid >> 2;          // 0..63
    int lk = (tid & 3) * 4;     // 0,4,8,12
    const float* Ag = A + (size_t)(bm + lr) * IN_DIM + lk;
    const float* Bg = B + (size_t)(bn + lr) * IN_DIM + lk;

    for (int k0 = 0; k0 < IN_DIM; k0 += BKK) {
        float4 a0 = *(const float4*)(Ag + k0);
        float4 a1 = *(const float4*)(Ag + (size_t)64 * IN_DIM + k0);
        float4 b0 = *(const float4*)(Bg + k0);
        float4 b1 = *(const float4*)(Bg + (size_t)64 * IN_DIM + k0);
        __syncthreads();
        As[lk+0][lr] = a0.x; As[lk+1][lr] = a0.y; As[lk+2][lr] = a0.z; As[lk+3][lr] = a0.w;
        As[lk+0][lr+64] = a1.x; As[lk+1][lr+64] = a1.y; As[lk+2][lr+64] = a1.z; As[lk+3][lr+64] = a1.w;
        Bs[lk+0][lr] = b0.x; Bs[lk+1][lr] = b0.y; Bs[lk+2][lr] = b0.z; Bs[lk+3][lr] = b0.w;
        Bs[lk+0][lr+64] = b1.x; Bs[lk+1][lr+64] = b1.y; Bs[lk+2][lr+64] = b1.z; Bs[lk+3][lr+64] = b1.w;
        __syncthreads();
        #pragma unroll
        for (int k = 0; k < BKK; ++k) {
            float4 av0 = *(const float4*)&As[k][tyy*4];
            float4 av1 = *(const float4*)&As[k][64 + tyy*4];
            float4 bv0 = *(const float4*)&Bs[k][txx*4];
            float4 bv1 = *(const float4*)&Bs[k][64 + txx*4];
            float a[8] = {av0.x, av0.y, av0.z, av0.w, av1.x, av1.y, av1.z, av1.w};
            float b[8] = {bv0.x, bv0.y, bv0.z, bv0.w, bv1.x, bv1.y, bv1.z, bv1.w};
            #pragma unroll
            for (int i = 0; i < 8; ++i)
                #pragma unroll
                for (int j = 0; j < 8; ++j)
                    acc[i][j] += a[i] * b[j];
        }
    }

    float4 bl = *(const float4*)&bias[bn + txx*4];
    float4 bh = *(const float4*)&bias[bn + 64 + txx*4];
    #pragma unroll
    for (int i = 0; i < 8; ++i) {
        int r = bm + ((i < 4) ? (tyy*4 + i) : (64 + tyy*4 + i - 4));
        float4 lo, hi;
        lo.x = acc[i][0] + bl.x; lo.y = acc[i][1] + bl.y;
        lo.z = acc[i][2] + bl.z; lo.w = acc[i][3] + bl.w;
        hi.x = acc[i][4] + bh.x; hi.y = acc[i][5] + bh.y;
        hi.z = acc[i][6] + bh.z; hi.w = acc[i][7] + bh.w;
        *(float4*)&C[(size_t)r * LAT + bn + txx*4]      = lo;
        *(float4*)&C[(size_t)r * LAT + bn + 64 + txx*4] = hi;
    }
}

// ---------------- radix select: per-column k-th largest (exact 32-bit) ------
#define RSEL_COLS 32
__global__ __launch_bounds__(256)
void k_radix(const float* __restrict__ E, int pass) {
    __shared__ unsigned int hist[256][RSEL_COLS + 1];
    int colbase = blockIdx.x * RSEL_COLS;
    int tx = threadIdx.x & (RSEL_COLS - 1);
    int ty = threadIdx.x / RSEL_COLS;          // 0..7
    for (int i = threadIdx.x; i < 256 * (RSEL_COLS + 1); i += 256)
        ((unsigned int*)hist)[i] = 0u;
    __syncthreads();

    int col = colbase + tx;
    unsigned int pfx = g_prefix[col];
    int shift = 24 - 8 * pass;
    unsigned int pmask = (pass == 0) ? 0u : (0xFFFFFFFFu << (shift + 8));

    for (int r = ty; r < BATCH; r += 8) {
        float v = E[(size_t)r * LAT + col];
        unsigned int u = f2ord(v);
        if ((u & pmask) == (pfx & pmask))
            atomicAdd(&hist[(u >> shift) & 255][tx], 1u);
    }
    __syncthreads();

    if (threadIdx.x < RSEL_COLS) {
        int kr = g_krem[col];
        unsigned int cum = 0;
        int b = 255;
        for (; b >= 0; --b) {
            unsigned int h = hist[b][tx];
            cum += h;
            if ((int)cum >= kr) { kr -= (int)(cum - h); break; }
        }
        g_prefix[col] = pfx | ((unsigned int)b << shift);
        g_krem[col]   = kr;
    }
}

// ---------------- collect rows equal to threshold (for exact tie-break) -----
__global__ void k_eqscan(const float* __restrict__ E) {
    size_t idx = (size_t)blockIdx.x * blockDim.x + threadIdx.x;
    int row = (int)(idx >> 14);
    int col = (int)(idx & (LAT - 1));
    unsigned int u = f2ord(E[idx]);
    if (u == g_prefix[col]) {
        int p = atomicAdd(&g_eqcnt[col], 1);
        if (p < EQ_CAP) g_eqrows[col * EQ_CAP + p] = row;
    }
}

__global__ void k_eqsort() {
    int c = blockIdx.x * blockDim.x + threadIdx.x;
    if (c >= LAT) return;
    int n = g_eqcnt[c]; if (n > EQ_CAP) n = EQ_CAP;
    int* e = &g_eqrows[c * EQ_CAP];
    for (int i = 1; i < n; ++i) {            // insertion sort ascending
        int v = e[i]; int j = i - 1;
        while (j >= 0 && e[j] > v) { e[j+1] = e[j]; --j; }
        e[j+1] = v;
    }
    int kc = g_krem[c]; if (kc > n) kc = n;
    g_keepcnt[c] = kc;                        // keep lowest-index kc equals
}

// ---------------- mask in place + compact kept entries per row --------------
__global__ void k_out(float* __restrict__ E) {
    size_t idx = (size_t)blockIdx.x * blockDim.x + threadIdx.x;
    int row = (int)(idx >> 14);
    int col = (int)(idx & (LAT - 1));
    float v = E[idx];
    unsigned int u = f2ord(v);
    unsigned int T = g_prefix[col];
    bool keep = (u > T);
    if (u == T) {
        int kc = g_keepcnt[col];
        if (kc > EQ_CAP) kc = EQ_CAP;
        const int* e = &g_eqrows[col * EQ_CAP];
        for (int i = 0; i < kc; ++i)
            if (e[i] == row) { keep = true; break; }
    }
    if (keep) {
        int s = atomicAdd(&g_rown[row], 1);
        if (s < ROW_CAP) {
            g_rcols[(size_t)row * ROW_CAP + s] = col;
            g_rvals[(size_t)row * ROW_CAP + s] = v;
        }
    } else {
        E[idx] = 0.0f;
    }
}

// ---------------- sparse decoder gather -------------------------------------
__global__ void k_decode(const float* __restrict__ db, float* __restrict__ out) {
    int b = blockIdx.x;
    int t = threadIdx.x;                       // 256 threads, 768 = 3*256 outputs
    float acc0 = db[t], acc1 = db[t + 256], acc2 = db[t + 512];
    int n = g_rown[b]; if (n > ROW_CAP) n = ROW_CAP;
    const int*   cols = &g_rcols[(size_t)b * ROW_CAP];
    const float* vals = &g_rvals[(size_t)b * ROW_CAP];
    for (int e = 0; e < n; ++e) {
        int j = __ldg(&cols[e]);
        float v = __ldg(&vals[e]);
        const float* w = &g_dwt[(size_t)j * IN_DIM];
        acc0 += v * w[t];
        acc1 += v * w[t + 256];
        acc2 += v * w[t + 512];
    }
    out[(size_t)b * IN_DIM + t]       = acc0;
    out[(size_t)b * IN_DIM + t + 256] = acc1;
    out[(size_t)b * IN_DIM + t + 512] = acc2;
}

// ---------------- launch -----------------------------------------------------
extern "C" void kernel_launch(void* const* d_in, const int* in_sizes, int n_in,
                              void* d_out, int out_size) {
    const float* x     = (const float*)d_in[0];
    const float* enc_w = (const float*)d_in[1];
    const float* enc_b = (const float*)d_in[2];
    const float* dec_w = (const float*)d_in[3];
    const float* dec_b = (const float*)d_in[4];

    float* dec_out = (float*)d_out;                         // [BATCH][IN_DIM]
    float* sp      = dec_out + (size_t)BATCH * IN_DIM;      // [BATCH][LAT]

    k_init<<<LAT / 256, 256>>>();
    k_transpose<<<dim3(LAT / 32, IN_DIM / 32), dim3(32, 8)>>>(dec_w);
    k_sgemm<<<dim3(LAT / BN, BATCH / BM), 256>>>(x, enc_w, enc_b, sp);
    for (int p = 0; p < 4; ++p)
        k_radix<<<LAT / RSEL_COLS, 256>>>(sp, p);
    {
        size_t total = (size_t)BATCH * LAT;
        int blocks = (int)(total / 256);
        k_eqscan<<<blocks, 256>>>(sp);
        k_eqsort<<<LAT / 256, 256>>>();
        k_out<<<blocks, 256>>>(sp);
    }
    k_decode<<<BATCH, 256>>>(dec_b, dec_out);
}

// round 12
// speedup vs baseline: 1.7169x; 1.7169x over previous
#include <cuda_runtime.h>
#include <cuda_bf16.h>
#include <cstdint>

// Problem constants
#define BATCH   8192
#define IN_DIM  768
#define LAT     16384
#define K_TOP   81
#define ROW_CAP 1024
#define CAND_CAP 128
#define DELTA   6e-4f

// GEMM config: C[BATCH][LAT] = Abig[BATCH][KS]*Bbig[LAT][KS]^T + bias
// 3-term bf16 split: A=[h|h|m], B=[h|m|h] -> hh + hm + mh (err ~1e-5 rms)
#define KS      2304              // 3*768
#define BM      128
#define BN      128
#define BKB     64                // bf16 per k-stage (=128B row)
#define NK      (KS / BKB)        // 36
#define NSTG    3
#define STG_BYTES (BM*BKB*2 + BN*BKB*2)   // 32768
#define SMEM_GEMM (NSTG * STG_BYTES)      // 98304

// ---------------- device scratch ----------------
__device__ __align__(16) __nv_bfloat16 g_Abf[(size_t)BATCH * KS];
__device__ __align__(16) __nv_bfloat16 g_Bbf[(size_t)LAT * KS];
__device__ float        g_dwt[(size_t)LAT * IN_DIM];
__device__ unsigned int g_prefix[LAT];
__device__ int          g_krem[LAT];
__device__ float        g_loT[LAT];
__device__ float        g_hiT[LAT];
__device__ int          g_defcnt[LAT];
__device__ int          g_candcnt[LAT];
__device__ int          g_keepn[LAT];
__device__ int          g_candrow[(size_t)LAT * CAND_CAP];
__device__ float        g_candval[(size_t)LAT * CAND_CAP];
__device__ int          g_rown[BATCH];
__device__ int          g_rcols[(size_t)BATCH * ROW_CAP];
__device__ float        g_rvals[(size_t)BATCH * ROW_CAP];

// ---------------- helpers ----------------
__device__ __forceinline__ uint32_t smem_u32(const void* p) {
    uint32_t a;
    asm("{ .reg .u64 t; cvta.to.shared.u64 t, %1; cvt.u32.u64 %0, t; }" : "=r"(a) : "l"(p));
    return a;
}
#define SWZ(o) ((o) ^ ((((uint32_t)(o)) >> 3) & 0x70u))

__device__ __forceinline__ void cp16(uint32_t dst, const void* src) {
    asm volatile("cp.async.cg.shared.global [%0], [%1], 16;\n" :: "r"(dst), "l"(src) : "memory");
}
#define CP_COMMIT() asm volatile("cp.async.commit_group;\n" ::: "memory")
#define CP_WAIT1()  asm volatile("cp.async.wait_group 1;\n" ::: "memory")

__device__ __forceinline__ unsigned int f2ord(float f) {
    unsigned int u = __float_as_uint(f);
    return u ^ ((u & 0x80000000u) ? 0xFFFFFFFFu : 0x80000000u);
}
__device__ __forceinline__ float ord2f(unsigned int o) {
    unsigned int u = (o & 0x80000000u) ? (o ^ 0x80000000u) : ~o;
    return __uint_as_float(u);
}

// ---------------- init ----------------
__global__ void k_init() {
    int i = blockIdx.x * blockDim.x + threadIdx.x;
    if (i < LAT) {
        g_prefix[i]  = 0u;
        g_krem[i]    = K_TOP;
        g_defcnt[i]  = 0;
        g_candcnt[i] = 0;
        g_keepn[i]   = 0;
    }
    if (i < BATCH) g_rown[i] = 0;
}

// ---------------- bf16 2-term splits (3 cross products) ----------------
__global__ void k_splitA(const float* __restrict__ X) {
    size_t idx = (size_t)blockIdx.x * blockDim.x + threadIdx.x;  // BATCH*IN_DIM
    int r = (int)(idx / IN_DIM);
    int k = (int)(idx % IN_DIM);
    float x = X[idx];
    __nv_bfloat16 h = __float2bfloat16_rn(x);
    __nv_bfloat16 m = __float2bfloat16_rn(x - __bfloat162float(h));
    __nv_bfloat16* A = g_Abf + (size_t)r * KS + k;
    A[0] = h; A[768] = h; A[1536] = m;
}
__global__ void k_splitB(const float* __restrict__ W) {
    size_t idx = (size_t)blockIdx.x * blockDim.x + threadIdx.x;  // LAT*IN_DIM
    int r = (int)(idx / IN_DIM);
    int k = (int)(idx % IN_DIM);
    float x = W[idx];
    __nv_bfloat16 h = __float2bfloat16_rn(x);
    __nv_bfloat16 m = __float2bfloat16_rn(x - __bfloat162float(h));
    __nv_bfloat16* B = g_Bbf + (size_t)r * KS + k;
    B[0] = h; B[768] = m; B[1536] = h;
}

// ---------------- transpose dec_w ----------------
__global__ void k_transpose(const float* __restrict__ dw) {
    __shared__ float t[32][33];
    int bx = blockIdx.x * 32;
    int by = blockIdx.y * 32;
    int x = bx + threadIdx.x;
    #pragma unroll
    for (int i = 0; i < 32; i += 8) {
        int y = by + threadIdx.y + i;
        t[threadIdx.y + i][threadIdx.x] = dw[(size_t)y * LAT + x];
    }
    __syncthreads();
    int xo = by + threadIdx.x;
    #pragma unroll
    for (int i = 0; i < 32; i += 8) {
        int yo = bx + threadIdx.y + i;
        g_dwt[(size_t)yo * IN_DIM + xo] = t[threadIdx.x][threadIdx.y + i];
    }
}

// ---------------- mma.sync bf16 GEMM ----------------
__global__ __launch_bounds__(256)
void k_hmma(const float* __restrict__ bias, float* __restrict__ C) {
    extern __shared__ char smem[];
    uint32_t sbase = smem_u32(smem);
    int tid  = threadIdx.x;
    int lane = tid & 31;
    int warp = tid >> 5;
    int wm = warp >> 2;       // 0-1 : 64-row slab
    int wn = warp & 3;        // 0-3 : 32-col slab

    // supertile: 8 groups of (64 bm x 16 bn) keep A(38MB)+B-slice(9.4MB) in L2
    int bid = blockIdx.x;
    int grp = bid >> 10;              // /1024
    int rem = bid & 1023;
    int bm  = rem & 63;
    int bn  = (grp << 4) | (rem >> 6);

    const __nv_bfloat16* Ag = g_Abf + (size_t)(bm * BM) * KS;
    const __nv_bfloat16* Bg = g_Bbf + (size_t)(bn * BN) * KS;

    int lrow = tid >> 3;      // 0-127
    int lchk = tid & 7;       // 0-7 (16B chunk)

    #define LOADSTG(slot, k0) do {                                                   \
        uint32_t _sa = sbase + (uint32_t)(slot) * STG_BYTES;                         \
        uint32_t _sb = _sa + BM * BKB * 2;                                           \
        uint32_t _off = (uint32_t)(lrow * 128 + lchk * 16);                          \
        cp16(_sa + SWZ(_off), Ag + (size_t)lrow * KS + (k0) + lchk * 8);             \
        cp16(_sb + SWZ(_off), Bg + (size_t)lrow * KS + (k0) + lchk * 8);             \
        _Pragma("unroll")                                                            \
        for (int _j = 1; _j < 4; ++_j) {                                             \
            int _ch = tid + 256 * _j; int _r = _ch >> 3; int _c = _ch & 7;           \
            uint32_t _o = (uint32_t)(_r * 128 + _c * 16);                            \
            cp16(_sa + SWZ(_o), Ag + (size_t)_r * KS + (k0) + _c * 8);               \
            cp16(_sb + SWZ(_o), Bg + (size_t)_r * KS + (k0) + _c * 8);               \
        }                                                                            \
        CP_COMMIT();                                                                 \
    } while (0)

    float acc[4][4][4];
    #pragma unroll
    for (int i = 0; i < 4; ++i)
        #pragma unroll
        for (int j = 0; j < 4; ++j)
            #pragma unroll
            for (int q = 0; q < 4; ++q) acc[i][j][q] = 0.0f;

    LOADSTG(0, 0);
    LOADSTG(1, BKB);

    // per-thread ldmatrix address pieces
    int arow = wm * 64 + (lane & 15);          // + mt*16
    int aside = (lane >> 4) & 1;               // 0/1 -> +16B
    int brow = wn * 32 + (lane & 7);           // + nt*8
    int bside = (lane >> 3) & 1;

    for (int i = 0; i < NK; ++i) {
        CP_WAIT1();
        __syncthreads();
        int slot = i % NSTG;
        uint32_t sa = sbase + (uint32_t)slot * STG_BYTES;
        uint32_t sb = sa + BM * BKB * 2;

        int nx = i + 2;
        if (nx < NK) LOADSTG(nx % NSTG, nx * BKB);
        else CP_COMMIT();

        #pragma unroll
        for (int ks = 0; ks < 4; ++ks) {
            uint32_t a[4][4], b[4][2];
            #pragma unroll
            for (int mt = 0; mt < 4; ++mt) {
                uint32_t off = (uint32_t)((arow + mt * 16) * 128 + ks * 32 + aside * 16);
                uint32_t ad = sa + SWZ(off);
                asm volatile("ldmatrix.sync.aligned.m8n8.x4.shared.b16 {%0,%1,%2,%3}, [%4];"
                    : "=r"(a[mt][0]), "=r"(a[mt][1]), "=r"(a[mt][2]), "=r"(a[mt][3]) : "r"(ad));
            }
            #pragma unroll
            for (int nt = 0; nt < 4; ++nt) {
                uint32_t off = (uint32_t)((brow + nt * 8) * 128 + ks * 32 + bside * 16);
                uint32_t bd = sb + SWZ(off);
                asm volatile("ldmatrix.sync.aligned.m8n8.x2.shared.b16 {%0,%1}, [%2];"
                    : "=r"(b[nt][0]), "=r"(b[nt][1]) : "r"(bd));
            }
            #pragma unroll
            for (int mt = 0; mt < 4; ++mt)
                #pragma unroll
                for (int nt = 0; nt < 4; ++nt) {
                    asm volatile(
                        "mma.sync.aligned.m16n8k16.row.col.f32.bf16.bf16.f32 "
                        "{%0,%1,%2,%3}, {%4,%5,%6,%7}, {%8,%9}, {%0,%1,%2,%3};"
                        : "+f"(acc[mt][nt][0]), "+f"(acc[mt][nt][1]),
                          "+f"(acc[mt][nt][2]), "+f"(acc[mt][nt][3])
                        : "r"(a[mt][0]), "r"(a[mt][1]), "r"(a[mt][2]), "r"(a[mt][3]),
                          "r"(b[nt][0]), "r"(b[nt][1]));
                }
        }
        __syncthreads();
    }

    // epilogue
    #pragma unroll
    for (int mt = 0; mt < 4; ++mt) {
        int r0 = bm * BM + wm * 64 + mt * 16 + (lane >> 2);
        #pragma unroll
        for (int nt = 0; nt < 4; ++nt) {
            int col = bn * BN + wn * 32 + nt * 8 + 2 * (lane & 3);
            float2 bv = *(const float2*)&bias[col];
            float2 o0 = { acc[mt][nt][0] + bv.x, acc[mt][nt][1] + bv.y };
            float2 o1 = { acc[mt][nt][2] + bv.x, acc[mt][nt][3] + bv.y };
            *(float2*)&C[(size_t)r0 * LAT + col]       = o0;
            *(float2*)&C[(size_t)(r0 + 8) * LAT + col] = o1;
        }
    }
}

// ---------------- radix select: 2 passes -> 16-bit class of 81st value ------
#define RSEL_COLS 32
__global__ __launch_bounds__(256)
void k_radix(const float* __restrict__ E, int pass) {
    __shared__ unsigned int hist[256][RSEL_COLS + 1];
    int colbase = blockIdx.x * RSEL_COLS;
    int tx = threadIdx.x & (RSEL_COLS - 1);
    int ty = threadIdx.x / RSEL_COLS;
    for (int i = threadIdx.x; i < 256 * (RSEL_COLS + 1); i += 256)
        ((unsigned int*)hist)[i] = 0u;
    __syncthreads();

    int col = colbase + tx;
    unsigned int pfx = g_prefix[col];
    int shift = 24 - 8 * pass;
    unsigned int pmask = (pass == 0) ? 0u : 0xFF000000u;

    for (int r = ty; r < BATCH; r += 8) {
        float v = E[(size_t)r * LAT + col];
        unsigned int u = f2ord(v);
        if ((u & pmask) == (pfx & pmask))
            atomicAdd(&hist[(u >> shift) & 255][tx], 1u);
    }
    __syncthreads();

    if (threadIdx.x < RSEL_COLS) {
        int kr = g_krem[col];
        unsigned int cum = 0;
        int b = 255;
        for (; b >= 0; --b) {
            unsigned int h = hist[b][tx];
            cum += h;
            if ((int)cum >= kr) { kr -= (int)(cum - h); break; }
        }
        g_prefix[col] = pfx | ((unsigned int)b << shift);
        g_krem[col]   = kr;
    }
}

// ---------------- band thresholds per column ----------------
__global__ void k_bounds() {
    int c = blockIdx.x * blockDim.x + threadIdx.x;
    if (c >= LAT) return;
    unsigned int pfx = g_prefix[c];            // top 16 bits valid
    g_loT[c] = ord2f(pfx) - 2.0f * DELTA;      // provably-out below this
    g_hiT[c] = ord2f(pfx | 0xFFFFu) + DELTA;   // provably-in above this
}

// ---------------- collect band candidates + definite counts ----------------
__global__ void k_collect(const float* __restrict__ E) {
    size_t idx = (size_t)blockIdx.x * blockDim.x + threadIdx.x;
    int col = (int)(idx & (LAT - 1));
    int row = (int)(idx >> 14);
    float v = E[idx];
    float hi = g_hiT[col];
    if (v > hi) {
        atomicAdd(&g_defcnt[col], 1);
    } else if (v >= g_loT[col]) {
        int p = atomicAdd(&g_candcnt[col], 1);
        if (p < CAND_CAP) g_candrow[(size_t)col * CAND_CAP + p] = row;
    }
}

// ---------------- exact fp32 dot for candidates ---------------------------
// CRITICAL: sequential ascending-k fmaf chain, one thread per candidate —
// bit-identical arithmetic to the R2 fp32 SGEMM whose selection passed.
__global__ __launch_bounds__(128)
void k_exact(const float* __restrict__ X, const float* __restrict__ W,
             const float* __restrict__ eb) {
    int col = blockIdx.x;
    int nc = g_candcnt[col]; if (nc > CAND_CAP) nc = CAND_CAP;
    int ci = threadIdx.x;
    if (ci >= nc) return;
    int row = g_candrow[(size_t)col * CAND_CAP + ci];
    const float* x = X + (size_t)row * IN_DIM;
    const float* w = W + (size_t)col * IN_DIM;
    float s = 0.0f;
    for (int k = 0; k < IN_DIM; k += 4) {         // sequential order preserved
        float4 xv = *(const float4*)&x[k];
        float4 wv = *(const float4*)&w[k];
        s = fmaf(xv.x, wv.x, s);
        s = fmaf(xv.y, wv.y, s);
        s = fmaf(xv.z, wv.z, s);
        s = fmaf(xv.w, wv.w, s);
    }
    g_candval[(size_t)col * CAND_CAP + ci] = s + eb[col];
}

// ---------------- choose top (81 - defcnt) candidates exactly ----------------
__global__ void k_select() {
    int c = blockIdx.x * blockDim.x + threadIdx.x;
    if (c >= LAT) return;
    int nc = g_candcnt[c]; if (nc > CAND_CAP) nc = CAND_CAP;
    int need = K_TOP - g_defcnt[c];
    if (need < 0) need = 0;
    if (need > nc) need = nc;
    int*   cr = &g_candrow[(size_t)c * CAND_CAP];
    float* cv = &g_candval[(size_t)c * CAND_CAP];
    for (int i = 0; i < need; ++i) {           // partial selection sort
        int best = i;
        unsigned int bo = f2ord(cv[best]);
        for (int j = i + 1; j < nc; ++j) {
            unsigned int jo = f2ord(cv[j]);
            if (jo > bo || (jo == bo && cr[j] < cr[best])) { best = j; bo = jo; }
        }
        if (best != i) {
            int tr = cr[i]; cr[i] = cr[best]; cr[best] = tr;
            float tv = cv[i]; cv[i] = cv[best]; cv[best] = tv;
        }
    }
    g_keepn[c] = need;
}

// ---------------- mask in place + per-row compaction ----------------
__global__ void k_out(float* __restrict__ E) {
    size_t idx = (size_t)blockIdx.x * blockDim.x + threadIdx.x;
    int col = (int)(idx & (LAT - 1));
    int row = (int)(idx >> 14);
    float v = E[idx];
    bool keep = false;
    if (v > g_hiT[col]) keep = true;
    else if (v >= g_loT[col]) {
        int n = g_keepn[col];
        const int* cr = &g_candrow[(size_t)col * CAND_CAP];
        for (int i = 0; i < n; ++i)
            if (cr[i] == row) { keep = true; break; }
    }
    if (keep) {
        int s = atomicAdd(&g_rown[row], 1);
        if (s < ROW_CAP) {
            g_rcols[(size_t)row * ROW_CAP + s] = col;
            g_rvals[(size_t)row * ROW_CAP + s] = v;
        }
    } else {
        E[idx] = 0.0f;
    }
}

// ---------------- sparse decoder gather ----------------
__global__ void k_decode(const float* __restrict__ db, float* __restrict__ out) {
    int b = blockIdx.x;
    int t = threadIdx.x;
    float acc0 = db[t], acc1 = db[t + 256], acc2 = db[t + 512];
    int n = g_rown[b]; if (n > ROW_CAP) n = ROW_CAP;
    const int*   cols = &g_rcols[(size_t)b * ROW_CAP];
    const float* vals = &g_rvals[(size_t)b * ROW_CAP];
    for (int e = 0; e < n; ++e) {
        int j = __ldg(&cols[e]);
        float v = __ldg(&vals[e]);
        const float* w = &g_dwt[(size_t)j * IN_DIM];
        acc0 += v * w[t];
        acc1 += v * w[t + 256];
        acc2 += v * w[t + 512];
    }
    out[(size_t)b * IN_DIM + t]       = acc0;
    out[(size_t)b * IN_DIM + t + 256] = acc1;
    out[(size_t)b * IN_DIM + t + 512] = acc2;
}

// ---------------- launch ----------------
extern "C" void kernel_launch(void* const* d_in, const int* in_sizes, int n_in,
                              void* d_out, int out_size) {
    const float* x     = (const float*)d_in[0];
    const float* enc_w = (const float*)d_in[1];
    const float* enc_b = (const float*)d_in[2];
    const float* dec_w = (const float*)d_in[3];
    const float* dec_b = (const float*)d_in[4];

    float* dec_out = (float*)d_out;
    float* sp      = dec_out + (size_t)BATCH * IN_DIM;

    cudaFuncSetAttribute(k_hmma, cudaFuncAttributeMaxDynamicSharedMemorySize, SMEM_GEMM);

    k_init<<<LAT / 256, 256>>>();
    k_splitA<<<(BATCH * IN_DIM) / 256, 256>>>(x);
    k_splitB<<<(LAT * IN_DIM) / 256, 256>>>(enc_w);
    k_transpose<<<dim3(LAT / 32, IN_DIM / 32), dim3(32, 8)>>>(dec_w);

    k_hmma<<<(BATCH / BM) * (LAT / BN), 256, SMEM_GEMM>>>(enc_b, sp);

    k_radix<<<LAT / RSEL_COLS, 256>>>(sp, 0);
    k_radix<<<LAT / RSEL_COLS, 256>>>(sp, 1);
    k_bounds<<<LAT / 256, 256>>>();
    {
        int blocks = (int)(((size_t)BATCH * LAT) / 256);
        k_collect<<<blocks, 256>>>(sp);
        k_exact<<<LAT, 128>>>(x, enc_w, enc_b);
        k_select<<<LAT / 256, 256>>>();
        k_out<<<blocks, 256>>>(sp);
    }
    k_decode<<<BATCH, 256>>>(dec_b, dec_out);
}

// round 13
// speedup vs baseline: 1.7756x; 1.0342x over previous
#include <cuda_runtime.h>
#include <cuda_bf16.h>
#include <cstdint>

// Problem constants
#define BATCH   8192
#define IN_DIM  768
#define LAT     16384
#define K_TOP   81
#define ROW_CAP 1024
#define CAND_CAP 128
#define DELTA   6e-4f

// GEMM config (verified R12: 3394us total, rel_err 4.3e-6)
#define KS      2304
#define BM      128
#define BN      128
#define BKB     64
#define NK      (KS / BKB)
#define NSTG    3
#define STG_BYTES (BM*BKB*2 + BN*BKB*2)
#define SMEM_GEMM (NSTG * STG_BYTES)      // 98304

// ---------------- device scratch ----------------
__device__ __align__(16) __nv_bfloat16 g_Abf[(size_t)BATCH * KS];
__device__ __align__(16) __nv_bfloat16 g_Bbf[(size_t)LAT * KS];
__device__ float        g_dwt[(size_t)LAT * IN_DIM];
__device__ unsigned int g_prefix[LAT];
__device__ int          g_krem[LAT];
__device__ float        g_loT[LAT];
__device__ float        g_hiT[LAT];
__device__ int          g_defcnt[LAT];
__device__ int          g_candcnt[LAT];
__device__ int          g_keepn[LAT];
__device__ int          g_candrow[(size_t)LAT * CAND_CAP];
__device__ float        g_candval[(size_t)LAT * CAND_CAP];
__device__ int          g_rown[BATCH];
__device__ int          g_rcols[(size_t)BATCH * ROW_CAP];
__device__ float        g_rvals[(size_t)BATCH * ROW_CAP];

// ---------------- helpers ----------------
__device__ __forceinline__ uint32_t smem_u32(const void* p) {
    uint32_t a;
    asm("{ .reg .u64 t; cvta.to.shared.u64 t, %1; cvt.u32.u64 %0, t; }" : "=r"(a) : "l"(p));
    return a;
}
#define SWZ(o) ((o) ^ ((((uint32_t)(o)) >> 3) & 0x70u))

__device__ __forceinline__ void cp16(uint32_t dst, const void* src) {
    asm volatile("cp.async.cg.shared.global [%0], [%1], 16;\n" :: "r"(dst), "l"(src) : "memory");
}
#define CP_COMMIT() asm volatile("cp.async.commit_group;\n" ::: "memory")
#define CP_WAIT1()  asm volatile("cp.async.wait_group 1;\n" ::: "memory")

__device__ __forceinline__ unsigned int f2ord(float f) {
    unsigned int u = __float_as_uint(f);
    return u ^ ((u & 0x80000000u) ? 0xFFFFFFFFu : 0x80000000u);
}
__device__ __forceinline__ float ord2f(unsigned int o) {
    unsigned int u = (o & 0x80000000u) ? (o ^ 0x80000000u) : ~o;
    return __uint_as_float(u);
}

// ---------------- init ----------------
__global__ void k_init() {
    int i = blockIdx.x * blockDim.x + threadIdx.x;
    if (i < LAT) {
        g_prefix[i]  = 0u;
        g_krem[i]    = K_TOP;
        g_candcnt[i] = 0;
        g_keepn[i]   = 0;
    }
    if (i < BATCH) g_rown[i] = 0;
}

// ---------------- bf16 2-term splits (3 cross products) ----------------
__global__ void k_splitA(const float* __restrict__ X) {
    size_t idx = (size_t)blockIdx.x * blockDim.x + threadIdx.x;
    int r = (int)(idx / IN_DIM);
    int k = (int)(idx % IN_DIM);
    float x = X[idx];
    __nv_bfloat16 h = __float2bfloat16_rn(x);
    __nv_bfloat16 m = __float2bfloat16_rn(x - __bfloat162float(h));
    __nv_bfloat16* A = g_Abf + (size_t)r * KS + k;
    A[0] = h; A[768] = h; A[1536] = m;
}
__global__ void k_splitB(const float* __restrict__ W) {
    size_t idx = (size_t)blockIdx.x * blockDim.x + threadIdx.x;
    int r = (int)(idx / IN_DIM);
    int k = (int)(idx % IN_DIM);
    float x = W[idx];
    __nv_bfloat16 h = __float2bfloat16_rn(x);
    __nv_bfloat16 m = __float2bfloat16_rn(x - __bfloat162float(h));
    __nv_bfloat16* B = g_Bbf + (size_t)r * KS + k;
    B[0] = h; B[768] = m; B[1536] = h;
}

// ---------------- transpose dec_w ----------------
__global__ void k_transpose(const float* __restrict__ dw) {
    __shared__ float t[32][33];
    int bx = blockIdx.x * 32;
    int by = blockIdx.y * 32;
    int x = bx + threadIdx.x;
    #pragma unroll
    for (int i = 0; i < 32; i += 8) {
        int y = by + threadIdx.y + i;
        t[threadIdx.y + i][threadIdx.x] = dw[(size_t)y * LAT + x];
    }
    __syncthreads();
    int xo = by + threadIdx.x;
    #pragma unroll
    for (int i = 0; i < 32; i += 8) {
        int yo = bx + threadIdx.y + i;
        g_dwt[(size_t)yo * IN_DIM + xo] = t[threadIdx.x][threadIdx.y + i];
    }
}

// ---------------- mma.sync bf16 GEMM (verified core; +min-2-blocks hint) ----
__global__ __launch_bounds__(256, 2)
void k_hmma(const float* __restrict__ bias, float* __restrict__ C) {
    extern __shared__ char smem[];
    uint32_t sbase = smem_u32(smem);
    int tid  = threadIdx.x;
    int lane = tid & 31;
    int warp = tid >> 5;
    int wm = warp >> 2;
    int wn = warp & 3;

    int bid = blockIdx.x;
    int grp = bid >> 10;
    int rem = bid & 1023;
    int bm  = rem & 63;
    int bn  = (grp << 4) | (rem >> 6);

    const __nv_bfloat16* Ag = g_Abf + (size_t)(bm * BM) * KS;
    const __nv_bfloat16* Bg = g_Bbf + (size_t)(bn * BN) * KS;

    int lrow = tid >> 3;
    int lchk = tid & 7;

    #define LOADSTG(slot, k0) do {                                                   \
        uint32_t _sa = sbase + (uint32_t)(slot) * STG_BYTES;                         \
        uint32_t _sb = _sa + BM * BKB * 2;                                           \
        uint32_t _off = (uint32_t)(lrow * 128 + lchk * 16);                          \
        cp16(_sa + SWZ(_off), Ag + (size_t)lrow * KS + (k0) + lchk * 8);             \
        cp16(_sb + SWZ(_off), Bg + (size_t)lrow * KS + (k0) + lchk * 8);             \
        _Pragma("unroll")                                                            \
        for (int _j = 1; _j < 4; ++_j) {                                             \
            int _ch = tid + 256 * _j; int _r = _ch >> 3; int _c = _ch & 7;           \
            uint32_t _o = (uint32_t)(_r * 128 + _c * 16);                            \
            cp16(_sa + SWZ(_o), Ag + (size_t)_r * KS + (k0) + _c * 8);               \
            cp16(_sb + SWZ(_o), Bg + (size_t)_r * KS + (k0) + _c * 8);               \
        }                                                                            \
        CP_COMMIT();                                                                 \
    } while (0)

    float acc[4][4][4];
    #pragma unroll
    for (int i = 0; i < 4; ++i)
        #pragma unroll
        for (int j = 0; j < 4; ++j)
            #pragma unroll
            for (int q = 0; q < 4; ++q) acc[i][j][q] = 0.0f;

    LOADSTG(0, 0);
    LOADSTG(1, BKB);

    int arow = wm * 64 + (lane & 15);
    int aside = (lane >> 4) & 1;
    int brow = wn * 32 + (lane & 7);
    int bside = (lane >> 3) & 1;

    for (int i = 0; i < NK; ++i) {
        CP_WAIT1();
        __syncthreads();
        int slot = i % NSTG;
        uint32_t sa = sbase + (uint32_t)slot * STG_BYTES;
        uint32_t sb = sa + BM * BKB * 2;

        int nx = i + 2;
        if (nx < NK) LOADSTG(nx % NSTG, nx * BKB);
        else CP_COMMIT();

        #pragma unroll
        for (int ks = 0; ks < 4; ++ks) {
            uint32_t a[4][4], b[4][2];
            #pragma unroll
            for (int mt = 0; mt < 4; ++mt) {
                uint32_t off = (uint32_t)((arow + mt * 16) * 128 + ks * 32 + aside * 16);
                uint32_t ad = sa + SWZ(off);
                asm volatile("ldmatrix.sync.aligned.m8n8.x4.shared.b16 {%0,%1,%2,%3}, [%4];"
                    : "=r"(a[mt][0]), "=r"(a[mt][1]), "=r"(a[mt][2]), "=r"(a[mt][3]) : "r"(ad));
            }
            #pragma unroll
            for (int nt = 0; nt < 4; ++nt) {
                uint32_t off = (uint32_t)((brow + nt * 8) * 128 + ks * 32 + bside * 16);
                uint32_t bd = sb + SWZ(off);
                asm volatile("ldmatrix.sync.aligned.m8n8.x2.shared.b16 {%0,%1}, [%2];"
                    : "=r"(b[nt][0]), "=r"(b[nt][1]) : "r"(bd));
            }
            #pragma unroll
            for (int mt = 0; mt < 4; ++mt)
                #pragma unroll
                for (int nt = 0; nt < 4; ++nt) {
                    asm volatile(
                        "mma.sync.aligned.m16n8k16.row.col.f32.bf16.bf16.f32 "
                        "{%0,%1,%2,%3}, {%4,%5,%6,%7}, {%8,%9}, {%0,%1,%2,%3};"
                        : "+f"(acc[mt][nt][0]), "+f"(acc[mt][nt][1]),
                          "+f"(acc[mt][nt][2]), "+f"(acc[mt][nt][3])
                        : "r"(a[mt][0]), "r"(a[mt][1]), "r"(a[mt][2]), "r"(a[mt][3]),
                          "r"(b[nt][0]), "r"(b[nt][1]));
                }
        }
        __syncthreads();
    }

    #pragma unroll
    for (int mt = 0; mt < 4; ++mt) {
        int r0 = bm * BM + wm * 64 + mt * 16 + (lane >> 2);
        #pragma unroll
        for (int nt = 0; nt < 4; ++nt) {
            int col = bn * BN + wn * 32 + nt * 8 + 2 * (lane & 3);
            float2 bv = *(const float2*)&bias[col];
            float2 o0 = { acc[mt][nt][0] + bv.x, acc[mt][nt][1] + bv.y };
            float2 o1 = { acc[mt][nt][2] + bv.x, acc[mt][nt][3] + bv.y };
            *(float2*)&C[(size_t)r0 * LAT + col]       = o0;
            *(float2*)&C[(size_t)(r0 + 8) * LAT + col] = o1;
        }
    }
}

// ---------------- radix pass 0: top byte class ------------------------------
#define RSEL_COLS 32
__global__ __launch_bounds__(256)
void k_radix0(const float* __restrict__ E) {
    __shared__ unsigned int hist[256][RSEL_COLS + 1];
    int colbase = blockIdx.x * RSEL_COLS;
    int tx = threadIdx.x & (RSEL_COLS - 1);
    int ty = threadIdx.x / RSEL_COLS;
    for (int i = threadIdx.x; i < 256 * (RSEL_COLS + 1); i += 256)
        ((unsigned int*)hist)[i] = 0u;
    __syncthreads();

    int col = colbase + tx;
    for (int r = ty; r < BATCH; r += 8) {
        float v = E[(size_t)r * LAT + col];
        unsigned int u = f2ord(v);
        atomicAdd(&hist[u >> 24][tx], 1u);
    }
    __syncthreads();

    if (threadIdx.x < RSEL_COLS) {
        int kr = K_TOP;
        unsigned int cum = 0;
        int b = 255;
        for (; b >= 0; --b) {
            unsigned int h = hist[b][tx];
            cum += h;
            if ((int)cum >= kr) { kr -= (int)(cum - h); break; }
        }
        g_prefix[col] = (unsigned int)b << 24;
        g_krem[col]   = kr;
    }
}

// ---------------- radix pass 1 fused with bounds + collect ------------------
// Histogram of byte 2 within the pass-0 class, then bounds, then an L2-hot
// re-scan of the same column slab for defcnt + band candidates.
__global__ __launch_bounds__(256)
void k_radix1c(const float* __restrict__ E) {
    __shared__ unsigned int hist[256][RSEL_COLS + 1];
    __shared__ float s_lo[RSEL_COLS], s_hi[RSEL_COLS];
    __shared__ int   s_def[RSEL_COLS];
    int colbase = blockIdx.x * RSEL_COLS;
    int tx = threadIdx.x & (RSEL_COLS - 1);
    int ty = threadIdx.x / RSEL_COLS;
    for (int i = threadIdx.x; i < 256 * (RSEL_COLS + 1); i += 256)
        ((unsigned int*)hist)[i] = 0u;
    __syncthreads();

    int col = colbase + tx;
    unsigned int pfx = g_prefix[col];
    for (int r = ty; r < BATCH; r += 8) {
        float v = E[(size_t)r * LAT + col];
        unsigned int u = f2ord(v);
        if ((u & 0xFF000000u) == pfx)
            atomicAdd(&hist[(u >> 16) & 255][tx], 1u);
    }
    __syncthreads();

    if (threadIdx.x < RSEL_COLS) {
        int kr = g_krem[col];
        unsigned int cum = 0;
        int b = 255;
        for (; b >= 0; --b) {
            unsigned int h = hist[b][tx];
            cum += h;
            if ((int)cum >= kr) { kr -= (int)(cum - h); break; }
        }
        unsigned int pfx2 = pfx | ((unsigned int)b << 16);
        g_krem[col] = kr;
        float lo = ord2f(pfx2) - 2.0f * DELTA;            // provably-out below
        float hi = ord2f(pfx2 | 0xFFFFu) + DELTA;         // provably-in above
        g_loT[col] = lo; g_hiT[col] = hi;
        s_lo[threadIdx.x] = lo; s_hi[threadIdx.x] = hi; s_def[threadIdx.x] = 0;
    }
    __syncthreads();

    // re-scan (mostly L2-hot) for definite count + band candidates
    float lo = s_lo[tx], hi = s_hi[tx];
    int mydef = 0;
    for (int r = ty; r < BATCH; r += 8) {
        float v = E[(size_t)r * LAT + col];
        if (v > hi) {
            ++mydef;
        } else if (v >= lo) {
            int p = atomicAdd(&g_candcnt[col], 1);
            if (p < CAND_CAP) g_candrow[(size_t)col * CAND_CAP + p] = r;
        }
    }
    if (mydef) atomicAdd(&s_def[tx], mydef);
    __syncthreads();
    if (threadIdx.x < RSEL_COLS)
        g_defcnt[col] = s_def[threadIdx.x];
}

// ---------------- exact fp32 dot for candidates + fused selection ----------
// CRITICAL: sequential ascending-k fmaf chain, bit-identical to the R2 fp32
// SGEMM whose selection passed (verified again in R12 at rel_err 4.3e-6).
__global__ __launch_bounds__(128)
void k_exact(const float* __restrict__ X, const float* __restrict__ W,
             const float* __restrict__ eb) {
    int col = blockIdx.x;
    int nc = g_candcnt[col]; if (nc > CAND_CAP) nc = CAND_CAP;
    int ci = threadIdx.x;
    if (ci < nc) {
        int row = g_candrow[(size_t)col * CAND_CAP + ci];
        const float* x = X + (size_t)row * IN_DIM;
        const float* w = W + (size_t)col * IN_DIM;
        float s = 0.0f;
        for (int k = 0; k < IN_DIM; k += 4) {
            float4 xv = *(const float4*)&x[k];
            float4 wv = *(const float4*)&w[k];
            s = fmaf(xv.x, wv.x, s);
            s = fmaf(xv.y, wv.y, s);
            s = fmaf(xv.z, wv.z, s);
            s = fmaf(xv.w, wv.w, s);
        }
        g_candval[(size_t)col * CAND_CAP + ci] = s + eb[col];
    }
    __syncthreads();
    if (threadIdx.x == 0) {
        int need = K_TOP - g_defcnt[col];
        if (need < 0) need = 0;
        if (need > nc) need = nc;
        int*   cr = &g_candrow[(size_t)col * CAND_CAP];
        float* cv = &g_candval[(size_t)col * CAND_CAP];
        for (int i = 0; i < need; ++i) {          // partial selection sort
            int best = i;
            unsigned int bo = f2ord(cv[best]);
            for (int j = i + 1; j < nc; ++j) {
                unsigned int jo = f2ord(cv[j]);
                if (jo > bo || (jo == bo && cr[j] < cr[best])) { best = j; bo = jo; }
            }
            if (best != i) {
                int tr = cr[i]; cr[i] = cr[best]; cr[best] = tr;
                float tv = cv[i]; cv[i] = cv[best]; cv[best] = tv;
            }
        }
        g_keepn[col] = need;
    }
}

// ---------------- mask in place + per-row compaction ----------------
__global__ void k_out(float* __restrict__ E) {
    size_t idx = (size_t)blockIdx.x * blockDim.x + threadIdx.x;
    int col = (int)(idx & (LAT - 1));
    int row = (int)(idx >> 14);
    float v = E[idx];
    bool keep = false;
    if (v > g_hiT[col]) keep = true;
    else if (v >= g_loT[col]) {
        int n = g_keepn[col];
        const int* cr = &g_candrow[(size_t)col * CAND_CAP];
        for (int i = 0; i < n; ++i)
            if (cr[i] == row) { keep = true; break; }
    }
    if (keep) {
        int s = atomicAdd(&g_rown[row], 1);
        if (s < ROW_CAP) {
            g_rcols[(size_t)row * ROW_CAP + s] = col;
            g_rvals[(size_t)row * ROW_CAP + s] = v;
        }
    } else {
        E[idx] = 0.0f;
    }
}

// ---------------- sparse decoder gather ----------------
__global__ void k_decode(const float* __restrict__ db, float* __restrict__ out) {
    int b = blockIdx.x;
    int t = threadIdx.x;
    float acc0 = db[t], acc1 = db[t + 256], acc2 = db[t + 512];
    int n = g_rown[b]; if (n > ROW_CAP) n = ROW_CAP;
    const int*   cols = &g_rcols[(size_t)b * ROW_CAP];
    const float* vals = &g_rvals[(size_t)b * ROW_CAP];
    for (int e = 0; e < n; ++e) {
        int j = __ldg(&cols[e]);
        float v = __ldg(&vals[e]);
        const float* w = &g_dwt[(size_t)j * IN_DIM];
        acc0 += v * w[t];
        acc1 += v * w[t + 256];
        acc2 += v * w[t + 512];
    }
    out[(size_t)b * IN_DIM + t]       = acc0;
    out[(size_t)b * IN_DIM + t + 256] = acc1;
    out[(size_t)b * IN_DIM + t + 512] = acc2;
}

// ---------------- launch ----------------
extern "C" void kernel_launch(void* const* d_in, const int* in_sizes, int n_in,
                              void* d_out, int out_size) {
    const float* x     = (const float*)d_in[0];
    const float* enc_w = (const float*)d_in[1];
    const float* enc_b = (const float*)d_in[2];
    const float* dec_w = (const float*)d_in[3];
    const float* dec_b = (const float*)d_in[4];

    float* dec_out = (float*)d_out;
    float* sp      = dec_out + (size_t)BATCH * IN_DIM;

    cudaFuncSetAttribute(k_hmma, cudaFuncAttributeMaxDynamicSharedMemorySize, SMEM_GEMM);

    k_init<<<LAT / 256, 256>>>();
    k_splitA<<<(BATCH * IN_DIM) / 256, 256>>>(x);
    k_splitB<<<(LAT * IN_DIM) / 256, 256>>>(enc_w);
    k_transpose<<<dim3(LAT / 32, IN_DIM / 32), dim3(32, 8)>>>(dec_w);

    k_hmma<<<(BATCH / BM) * (LAT / BN), 256, SMEM_GEMM>>>(enc_b, sp);

    k_radix0<<<LAT / RSEL_COLS, 256>>>(sp);
    k_radix1c<<<LAT / RSEL_COLS, 256>>>(sp);
    {
        int blocks = (int)(((size_t)BATCH * LAT) / 256);
        k_exact<<<LAT, 128>>>(x, enc_w, enc_b);
        k_out<<<blocks, 256>>>(sp);
    }
    k_decode<<<BATCH, 256>>>(dec_b, dec_out);
}

// round 15
// speedup vs baseline: 1.8865x; 1.0625x over previous
#include <cuda_runtime.h>
#include <cuda_bf16.h>
#include <cstdint>

// Problem constants
#define BATCH   8192
#define IN_DIM  768
#define LAT     16384
#define K_TOP   81
#define ROW_CAP 1024
#define CAND_CAP 128
#define EPSB    0.025f          // bound on 1-product bf16 GEMM error (~8 sigma)

// GEMM config: pure-h bf16, K=768 (selection protected by band + exact recompute;
// kept values repaired exactly afterwards)
#define KS      768
#define BM      128
#define BN      128
#define BKB     64
#define NK      (KS / BKB)                 // 12
#define NSTG    3
#define STG_BYTES (BM*BKB*2 + BN*BKB*2)
#define SMEM_GEMM (NSTG * STG_BYTES)       // 98304

// ---------------- device scratch ----------------
__device__ __align__(16) __nv_bfloat16 g_Abf[(size_t)BATCH * KS];
__device__ __align__(16) __nv_bfloat16 g_Bbf[(size_t)LAT * KS];
__device__ float        g_dwt[(size_t)LAT * IN_DIM];
__device__ unsigned int g_prefix[LAT];
__device__ int          g_krem[LAT];
__device__ float        g_loT[LAT];
__device__ float        g_hiT[LAT];
__device__ int          g_defcnt[LAT];
__device__ int          g_candcnt[LAT];
__device__ int          g_keepn[LAT];
__device__ int          g_candrow[(size_t)LAT * CAND_CAP];
__device__ float        g_candval[(size_t)LAT * CAND_CAP];
__device__ int          g_rown[BATCH];
__device__ int          g_rcols[(size_t)BATCH * ROW_CAP];

// ---------------- helpers ----------------
__device__ __forceinline__ uint32_t smem_u32(const void* p) {
    uint32_t a;
    asm("{ .reg .u64 t; cvta.to.shared.u64 t, %1; cvt.u32.u64 %0, t; }" : "=r"(a) : "l"(p));
    return a;
}
#define SWZ(o) ((o) ^ ((((uint32_t)(o)) >> 3) & 0x70u))

__device__ __forceinline__ void cp16(uint32_t dst, const void* src) {
    asm volatile("cp.async.cg.shared.global [%0], [%1], 16;\n" :: "r"(dst), "l"(src) : "memory");
}
#define CP_COMMIT() asm volatile("cp.async.commit_group;\n" ::: "memory")
#define CP_WAIT1()  asm volatile("cp.async.wait_group 1;\n" ::: "memory")

__device__ __forceinline__ unsigned int f2ord(float f) {
    unsigned int u = __float_as_uint(f);
    return u ^ ((u & 0x80000000u) ? 0xFFFFFFFFu : 0x80000000u);
}
__device__ __forceinline__ float ord2f(unsigned int o) {
    unsigned int u = (o & 0x80000000u) ? (o ^ 0x80000000u) : ~o;
    return __uint_as_float(u);
}

// ---------------- init ----------------
__global__ void k_init() {
    int i = blockIdx.x * blockDim.x + threadIdx.x;
    if (i < LAT) {
        g_prefix[i]  = 0u;
        g_krem[i]    = K_TOP;
        g_candcnt[i] = 0;
        g_keepn[i]   = 0;
    }
    if (i < BATCH) g_rown[i] = 0;
}

// ---------------- bf16 converts (h only) ----------------
__global__ void k_cvtA(const float* __restrict__ X) {
    size_t idx = (size_t)blockIdx.x * blockDim.x + threadIdx.x;   // BATCH*IN_DIM/2
    float2 v = ((const float2*)X)[idx];
    __nv_bfloat162 h;
    h.x = __float2bfloat16_rn(v.x);
    h.y = __float2bfloat16_rn(v.y);
    ((__nv_bfloat162*)g_Abf)[idx] = h;
}
__global__ void k_cvtB(const float* __restrict__ W) {
    size_t idx = (size_t)blockIdx.x * blockDim.x + threadIdx.x;   // LAT*IN_DIM/2
    float2 v = ((const float2*)W)[idx];
    __nv_bfloat162 h;
    h.x = __float2bfloat16_rn(v.x);
    h.y = __float2bfloat16_rn(v.y);
    ((__nv_bfloat162*)g_Bbf)[idx] = h;
}

// ---------------- transpose dec_w ----------------
__global__ void k_transpose(const float* __restrict__ dw) {
    __shared__ float t[32][33];
    int bx = blockIdx.x * 32;
    int by = blockIdx.y * 32;
    int x = bx + threadIdx.x;
    #pragma unroll
    for (int i = 0; i < 32; i += 8) {
        int y = by + threadIdx.y + i;
        t[threadIdx.y + i][threadIdx.x] = dw[(size_t)y * LAT + x];
    }
    __syncthreads();
    int xo = by + threadIdx.x;
    #pragma unroll
    for (int i = 0; i < 32; i += 8) {
        int yo = bx + threadIdx.y + i;
        g_dwt[(size_t)yo * IN_DIM + xo] = t[threadIdx.x][threadIdx.y + i];
    }
}

// ---------------- mma.sync bf16 GEMM (verified core; K=768) ----------------
__global__ __launch_bounds__(256, 2)
void k_hmma(const float* __restrict__ bias, float* __restrict__ C) {
    extern __shared__ char smem[];
    uint32_t sbase = smem_u32(smem);
    int tid  = threadIdx.x;
    int lane = tid & 31;
    int warp = tid >> 5;
    int wm = warp >> 2;
    int wn = warp & 3;

    int bid = blockIdx.x;
    int grp = bid >> 10;
    int rem = bid & 1023;
    int bm  = rem & 63;
    int bn  = (grp << 4) | (rem >> 6);

    const __nv_bfloat16* Ag = g_Abf + (size_t)(bm * BM) * KS;
    const __nv_bfloat16* Bg = g_Bbf + (size_t)(bn * BN) * KS;

    int lrow = tid >> 3;
    int lchk = tid & 7;

    #define LOADSTG(slot, k0) do {                                                   \
        uint32_t _sa = sbase + (uint32_t)(slot) * STG_BYTES;                         \
        uint32_t _sb = _sa + BM * BKB * 2;                                           \
        uint32_t _off = (uint32_t)(lrow * 128 + lchk * 16);                          \
        cp16(_sa + SWZ(_off), Ag + (size_t)lrow * KS + (k0) + lchk * 8);             \
        cp16(_sb + SWZ(_off), Bg + (size_t)lrow * KS + (k0) + lchk * 8);             \
        _Pragma("unroll")                                                            \
        for (int _j = 1; _j < 4; ++_j) {                                             \
            int _ch = tid + 256 * _j; int _r = _ch >> 3; int _c = _ch & 7;           \
            uint32_t _o = (uint32_t)(_r * 128 + _c * 16);                            \
            cp16(_sa + SWZ(_o), Ag + (size_t)_r * KS + (k0) + _c * 8);               \
            cp16(_sb + SWZ(_o), Bg + (size_t)_r * KS + (k0) + _c * 8);               \
        }                                                                            \
        CP_COMMIT();                                                                 \
    } while (0)

    float acc[4][4][4];
    #pragma unroll
    for (int i = 0; i < 4; ++i)
        #pragma unroll
        for (int j = 0; j < 4; ++j)
            #pragma unroll
            for (int q = 0; q < 4; ++q) acc[i][j][q] = 0.0f;

    LOADSTG(0, 0);
    LOADSTG(1, BKB);

    int arow = wm * 64 + (lane & 15);
    int aside = (lane >> 4) & 1;
    int brow = wn * 32 + (lane & 7);
    int bside = (lane >> 3) & 1;

    for (int i = 0; i < NK; ++i) {
        CP_WAIT1();
        __syncthreads();
        int slot = i % NSTG;
        uint32_t sa = sbase + (uint32_t)slot * STG_BYTES;
        uint32_t sb = sa + BM * BKB * 2;

        int nx = i + 2;
        if (nx < NK) LOADSTG(nx % NSTG, nx * BKB);
        else CP_COMMIT();

        #pragma unroll
        for (int ks = 0; ks < 4; ++ks) {
            uint32_t a[4][4], b[4][2];
            #pragma unroll
            for (int mt = 0; mt < 4; ++mt) {
                uint32_t off = (uint32_t)((arow + mt * 16) * 128 + ks * 32 + aside * 16);
                uint32_t ad = sa + SWZ(off);
                asm volatile("ldmatrix.sync.aligned.m8n8.x4.shared.b16 {%0,%1,%2,%3}, [%4];"
                    : "=r"(a[mt][0]), "=r"(a[mt][1]), "=r"(a[mt][2]), "=r"(a[mt][3]) : "r"(ad));
            }
            #pragma unroll
            for (int nt = 0; nt < 4; ++nt) {
                uint32_t off = (uint32_t)((brow + nt * 8) * 128 + ks * 32 + bside * 16);
                uint32_t bd = sb + SWZ(off);
                asm volatile("ldmatrix.sync.aligned.m8n8.x2.shared.b16 {%0,%1}, [%2];"
                    : "=r"(b[nt][0]), "=r"(b[nt][1]) : "r"(bd));
            }
            #pragma unroll
            for (int mt = 0; mt < 4; ++mt)
                #pragma unroll
                for (int nt = 0; nt < 4; ++nt) {
                    asm volatile(
                        "mma.sync.aligned.m16n8k16.row.col.f32.bf16.bf16.f32 "
                        "{%0,%1,%2,%3}, {%4,%5,%6,%7}, {%8,%9}, {%0,%1,%2,%3};"
                        : "+f"(acc[mt][nt][0]), "+f"(acc[mt][nt][1]),
                          "+f"(acc[mt][nt][2]), "+f"(acc[mt][nt][3])
                        : "r"(a[mt][0]), "r"(a[mt][1]), "r"(a[mt][2]), "r"(a[mt][3]),
                          "r"(b[nt][0]), "r"(b[nt][1]));
                }
        }
        __syncthreads();
    }

    #pragma unroll
    for (int mt = 0; mt < 4; ++mt) {
        int r0 = bm * BM + wm * 64 + mt * 16 + (lane >> 2);
        #pragma unroll
        for (int nt = 0; nt < 4; ++nt) {
            int col = bn * BN + wn * 32 + nt * 8 + 2 * (lane & 3);
            float2 bv = *(const float2*)&bias[col];
            float2 o0 = { acc[mt][nt][0] + bv.x, acc[mt][nt][1] + bv.y };
            float2 o1 = { acc[mt][nt][2] + bv.x, acc[mt][nt][3] + bv.y };
            *(float2*)&C[(size_t)r0 * LAT + col]       = o0;
            *(float2*)&C[(size_t)(r0 + 8) * LAT + col] = o1;
        }
    }
}

// ---------------- radix pass 0: top byte class ------------------------------
#define RSEL_COLS 32
__global__ __launch_bounds__(256)
void k_radix0(const float* __restrict__ E) {
    __shared__ unsigned int hist[256][RSEL_COLS + 1];
    int colbase = blockIdx.x * RSEL_COLS;
    int tx = threadIdx.x & (RSEL_COLS - 1);
    int ty = threadIdx.x / RSEL_COLS;
    for (int i = threadIdx.x; i < 256 * (RSEL_COLS + 1); i += 256)
        ((unsigned int*)hist)[i] = 0u;
    __syncthreads();

    int col = colbase + tx;
    for (int r = ty; r < BATCH; r += 8) {
        float v = E[(size_t)r * LAT + col];
        unsigned int u = f2ord(v);
        atomicAdd(&hist[u >> 24][tx], 1u);
    }
    __syncthreads();

    if (threadIdx.x < RSEL_COLS) {
        int kr = K_TOP;
        unsigned int cum = 0;
        int b = 255;
        for (; b >= 0; --b) {
            unsigned int h = hist[b][tx];
            cum += h;
            if ((int)cum >= kr) { kr -= (int)(cum - h); break; }
        }
        g_prefix[col] = (unsigned int)b << 24;
        g_krem[col]   = kr;
    }
}

// ---------------- radix pass 1 fused with bounds + collect ------------------
__global__ __launch_bounds__(256)
void k_radix1c(const float* __restrict__ E) {
    __shared__ unsigned int hist[256][RSEL_COLS + 1];
    __shared__ float s_lo[RSEL_COLS], s_hi[RSEL_COLS];
    __shared__ int   s_def[RSEL_COLS];
    int colbase = blockIdx.x * RSEL_COLS;
    int tx = threadIdx.x & (RSEL_COLS - 1);
    int ty = threadIdx.x / RSEL_COLS;
    for (int i = threadIdx.x; i < 256 * (RSEL_COLS + 1); i += 256)
        ((unsigned int*)hist)[i] = 0u;
    __syncthreads();

    int col = colbase + tx;
    unsigned int pfx = g_prefix[col];
    for (int r = ty; r < BATCH; r += 8) {
        float v = E[(size_t)r * LAT + col];
        unsigned int u = f2ord(v);
        if ((u & 0xFF000000u) == pfx)
            atomicAdd(&hist[(u >> 16) & 255][tx], 1u);
    }
    __syncthreads();

    if (threadIdx.x < RSEL_COLS) {
        int kr = g_krem[col];
        unsigned int cum = 0;
        int b = 255;
        for (; b >= 0; --b) {
            unsigned int h = hist[b][tx];
            cum += h;
            if ((int)cum >= kr) { kr -= (int)(cum - h); break; }
        }
        unsigned int pfx2 = pfx | ((unsigned int)b << 16);
        float lo = ord2f(pfx2) - 2.0f * EPSB;
        float hi = ord2f(pfx2 | 0xFFFFu) + 2.0f * EPSB;
        g_loT[col] = lo; g_hiT[col] = hi;
        s_lo[threadIdx.x] = lo; s_hi[threadIdx.x] = hi; s_def[threadIdx.x] = 0;
    }
    __syncthreads();

    float lo = s_lo[tx], hi = s_hi[tx];
    int mydef = 0;
    for (int r = ty; r < BATCH; r += 8) {
        float v = E[(size_t)r * LAT + col];
        if (v > hi) {
            ++mydef;
        } else if (v >= lo) {
            int p = atomicAdd(&g_candcnt[col], 1);
            if (p < CAND_CAP) g_candrow[(size_t)col * CAND_CAP + p] = r;
        }
    }
    if (mydef) atomicAdd(&s_def[tx], mydef);
    __syncthreads();
    if (threadIdx.x < RSEL_COLS)
        g_defcnt[col] = s_def[threadIdx.x];
}

// ---------------- exact fp32 dot for candidates + fused selection ----------
// Sequential ascending-k fmaf chain: bit-identical to the R2 fp32 SGEMM whose
// selection passed (re-verified R12/R13).
__global__ __launch_bounds__(128)
void k_exact(const float* __restrict__ X, const float* __restrict__ W,
             const float* __restrict__ eb) {
    int col = blockIdx.x;
    int nc = g_candcnt[col]; if (nc > CAND_CAP) nc = CAND_CAP;
    int ci = threadIdx.x;
    if (ci < nc) {
        int row = g_candrow[(size_t)col * CAND_CAP + ci];
        const float* x = X + (size_t)row * IN_DIM;
        const float* w = W + (size_t)col * IN_DIM;
        float s = 0.0f;
        for (int k = 0; k < IN_DIM; k += 4) {
            float4 xv = *(const float4*)&x[k];
            float4 wv = *(const float4*)&w[k];
            s = fmaf(xv.x, wv.x, s);
            s = fmaf(xv.y, wv.y, s);
            s = fmaf(xv.z, wv.z, s);
            s = fmaf(xv.w, wv.w, s);
        }
        g_candval[(size_t)col * CAND_CAP + ci] = s + eb[col];
    }
    __syncthreads();
    if (threadIdx.x == 0) {
        int need = K_TOP - g_defcnt[col];
        if (need < 0) need = 0;
        if (need > nc) need = nc;
        int*   cr = &g_candrow[(size_t)col * CAND_CAP];
        float* cv = &g_candval[(size_t)col * CAND_CAP];
        for (int i = 0; i < need; ++i) {
            int best = i;
            unsigned int bo = f2ord(cv[best]);
            for (int j = i + 1; j < nc; ++j) {
                unsigned int jo = f2ord(cv[j]);
                if (jo > bo || (jo == bo && cr[j] < cr[best])) { best = j; bo = jo; }
            }
            if (best != i) {
                int tr = cr[i]; cr[i] = cr[best]; cr[best] = tr;
                float tv = cv[i]; cv[i] = cv[best]; cv[best] = tv;
            }
        }
        g_keepn[col] = need;
    }
}

// ---------------- mask in place + per-row compaction ----------------
__global__ void k_out(float* __restrict__ E) {
    size_t idx = (size_t)blockIdx.x * blockDim.x + threadIdx.x;
    int col = (int)(idx & (LAT - 1));
    int row = (int)(idx >> 14);
    float v = E[idx];
    bool keep = false;
    if (v > g_hiT[col]) keep = true;
    else if (v >= g_loT[col]) {
        int n = g_keepn[col];
        const int* cr = &g_candrow[(size_t)col * CAND_CAP];
        for (int i = 0; i < n; ++i)
            if (cr[i] == row) { keep = true; break; }
    }
    if (keep) {
        int s = atomicAdd(&g_rown[row], 1);
        if (s < ROW_CAP) g_rcols[(size_t)row * ROW_CAP + s] = col;
    } else {
        E[idx] = 0.0f;
    }
}

// ---------------- exact repair of kept values (fp32) ----------------
// x[row] staged in smem; one warp per kept column; all operands L2-resident.
__global__ __launch_bounds__(256)
void k_repair(const float* __restrict__ X, const float* __restrict__ W,
              const float* __restrict__ eb, float* __restrict__ E) {
    __shared__ float xs[IN_DIM];
    int b = blockIdx.x;
    for (int i = threadIdx.x; i < IN_DIM; i += 256)
        xs[i] = X[(size_t)b * IN_DIM + i];
    __syncthreads();
    int n = g_rown[b]; if (n > ROW_CAP) n = ROW_CAP;
    int warp = threadIdx.x >> 5;
    int lane = threadIdx.x & 31;
    for (int e = warp; e < n; e += 8) {
        int col = g_rcols[(size_t)b * ROW_CAP + e];
        const float* w = W + (size_t)col * IN_DIM;
        float s = 0.0f;
        #pragma unroll 4
        for (int k = lane; k < IN_DIM; k += 32)
            s = fmaf(xs[k], w[k], s);
        #pragma unroll
        for (int o = 16; o > 0; o >>= 1)
            s += __shfl_xor_sync(0xFFFFFFFFu, s, o);
        if (lane == 0)
            E[(size_t)b * LAT + col] = s + eb[col];
    }
}

// ---------------- sparse decoder gather (reads repaired E) ----------------
__global__ void k_decode(const float* __restrict__ db, const float* __restrict__ E,
                         float* __restrict__ out) {
    int b = blockIdx.x;
    int t = threadIdx.x;
    float acc0 = db[t], acc1 = db[t + 256], acc2 = db[t + 512];
    int n = g_rown[b]; if (n > ROW_CAP) n = ROW_CAP;
    const int* cols = &g_rcols[(size_t)b * ROW_CAP];
    for (int e = 0; e < n; ++e) {
        int j = __ldg(&cols[e]);
        float v = __ldg(&E[(size_t)b * LAT + j]);
        const float* w = &g_dwt[(size_t)j * IN_DIM];
        acc0 += v * w[t];
        acc1 += v * w[t + 256];
        acc2 += v * w[t + 512];
    }
    out[(size_t)b * IN_DIM + t]       = acc0;
    out[(size_t)b * IN_DIM + t + 256] = acc1;
    out[(size_t)b * IN_DIM + t + 512] = acc2;
}

// ---------------- launch ----------------
extern "C" void kernel_launch(void* const* d_in, const int* in_sizes, int n_in,
                              void* d_out, int out_size) {
    const float* x     = (const float*)d_in[0];
    const float* enc_w = (const float*)d_in[1];
    const float* enc_b = (const float*)d_in[2];
    const float* dec_w = (const float*)d_in[3];
    const float* dec_b = (const float*)d_in[4];

    float* dec_out = (float*)d_out;
    float* sp      = dec_out + (size_t)BATCH * IN_DIM;

    cudaFuncSetAttribute(k_hmma, cudaFuncAttributeMaxDynamicSharedMemorySize, SMEM_GEMM);

    k_init<<<LAT / 256, 256>>>();
    k_cvtA<<<(BATCH * IN_DIM / 2) / 256, 256>>>(x);
    k_cvtB<<<(LAT * IN_DIM / 2) / 256, 256>>>(enc_w);
    k_transpose<<<dim3(LAT / 32, IN_DIM / 32), dim3(32, 8)>>>(dec_w);

    k_hmma<<<(BATCH / BM) * (LAT / BN), 256, SMEM_GEMM>>>(enc_b, sp);

    k_radix0<<<LAT / RSEL_COLS, 256>>>(sp);
    k_radix1c<<<LAT / RSEL_COLS, 256>>>(sp);
    {
        int blocks = (int)(((size_t)BATCH * LAT) / 256);
        k_exact<<<LAT, 128>>>(x, enc_w, enc_b);
        k_out<<<blocks, 256>>>(sp);
        k_repair<<<BATCH, 256>>>(x, enc_w, enc_b, sp);
    }
    k_decode<<<BATCH, 256>>>(dec_b, sp, dec_out);
}

// round 17
// speedup vs baseline: 2.2179x; 1.1757x over previous
#include <cuda_runtime.h>
#include <cuda_bf16.h>
#include <cstdint>

// Problem constants
#define BATCH   8192
#define IN_DIM  768
#define LAT     16384
#define K_TOP   81
#define ROW_CAP 1024
#define ROW_CAP_S 512           // smem copy cap in k_rd (per-row kept ~162)
#define CAND_CAP 128
#define EPSB    0.035f          // GEMM err (~0.025) + bf16 storage err (~0.005), 8-sigma-ish

// GEMM config: pure-h bf16, K=768, bf16 output scratch
#define KS      768
#define BM      128
#define BN      128
#define BKB     64
#define NK      (KS / BKB)                 // 12
#define NSTG    3
#define STG_BYTES (BM*BKB*2 + BN*BKB*2)
#define SMEM_GEMM (NSTG * STG_BYTES)       // 98304

// ---------------- device scratch ----------------
__device__ __align__(16) __nv_bfloat16 g_Abf[(size_t)BATCH * KS];
__device__ __align__(16) __nv_bfloat16 g_Bbf[(size_t)LAT * KS];
__device__ __align__(16) __nv_bfloat16 g_Ebf[(size_t)BATCH * LAT];   // GEMM out (approx)
__device__ float        g_dwt[(size_t)LAT * IN_DIM];
__device__ unsigned int g_prefix[LAT];
__device__ int          g_krem[LAT];
__device__ int          g_defcnt[LAT];
__device__ int          g_candcnt[LAT];
__device__ int          g_candrow[(size_t)LAT * CAND_CAP];
__device__ float        g_candval[(size_t)LAT * CAND_CAP];
__device__ int          g_rown[BATCH];
__device__ int          g_rcols[(size_t)BATCH * ROW_CAP];

// ---------------- helpers ----------------
__device__ __forceinline__ uint32_t smem_u32(const void* p) {
    uint32_t a;
    asm("{ .reg .u64 t; cvta.to.shared.u64 t, %1; cvt.u32.u64 %0, t; }" : "=r"(a) : "l"(p));
    return a;
}
#define SWZ(o) ((o) ^ ((((uint32_t)(o)) >> 3) & 0x70u))

__device__ __forceinline__ void cp16(uint32_t dst, const void* src) {
    asm volatile("cp.async.cg.shared.global [%0], [%1], 16;\n" :: "r"(dst), "l"(src) : "memory");
}
#define CP_COMMIT() asm volatile("cp.async.commit_group;\n" ::: "memory")
#define CP_WAIT1()  asm volatile("cp.async.wait_group 1;\n" ::: "memory")

__device__ __forceinline__ unsigned int f2ord(float f) {
    unsigned int u = __float_as_uint(f);
    return u ^ ((u & 0x80000000u) ? 0xFFFFFFFFu : 0x80000000u);
}
__device__ __forceinline__ float ord2f(unsigned int o) {
    unsigned int u = (o & 0x80000000u) ? (o ^ 0x80000000u) : ~o;
    return __uint_as_float(u);
}

// ---------------- init ----------------
__global__ void k_init() {
    int i = blockIdx.x * blockDim.x + threadIdx.x;
    if (i < LAT) g_candcnt[i] = 0;
    if (i < BATCH) g_rown[i] = 0;
}

// ---------------- bf16 converts (h only) ----------------
__global__ void k_cvtA(const float* __restrict__ X) {
    size_t idx = (size_t)blockIdx.x * blockDim.x + threadIdx.x;
    float2 v = ((const float2*)X)[idx];
    __nv_bfloat162 h;
    h.x = __float2bfloat16_rn(v.x);
    h.y = __float2bfloat16_rn(v.y);
    ((__nv_bfloat162*)g_Abf)[idx] = h;
}
__global__ void k_cvtB(const float* __restrict__ W) {
    size_t idx = (size_t)blockIdx.x * blockDim.x + threadIdx.x;
    float2 v = ((const float2*)W)[idx];
    __nv_bfloat162 h;
    h.x = __float2bfloat16_rn(v.x);
    h.y = __float2bfloat16_rn(v.y);
    ((__nv_bfloat162*)g_Bbf)[idx] = h;
}

// ---------------- transpose dec_w ----------------
__global__ void k_transpose(const float* __restrict__ dw) {
    __shared__ float t[32][33];
    int bx = blockIdx.x * 32;
    int by = blockIdx.y * 32;
    int x = bx + threadIdx.x;
    #pragma unroll
    for (int i = 0; i < 32; i += 8) {
        int y = by + threadIdx.y + i;
        t[threadIdx.y + i][threadIdx.x] = dw[(size_t)y * LAT + x];
    }
    __syncthreads();
    int xo = by + threadIdx.x;
    #pragma unroll
    for (int i = 0; i < 32; i += 8) {
        int yo = bx + threadIdx.y + i;
        g_dwt[(size_t)yo * IN_DIM + xo] = t[threadIdx.x][threadIdx.y + i];
    }
}

// ---------------- mma.sync bf16 GEMM (verified core; bf16 epilogue) ---------
__global__ __launch_bounds__(256, 2)
void k_hmma(const float* __restrict__ bias) {
    extern __shared__ char smem[];
    uint32_t sbase = smem_u32(smem);
    int tid  = threadIdx.x;
    int lane = tid & 31;
    int warp = tid >> 5;
    int wm = warp >> 2;
    int wn = warp & 3;

    int bid = blockIdx.x;
    int grp = bid >> 10;
    int rem = bid & 1023;
    int bm  = rem & 63;
    int bn  = (grp << 4) | (rem >> 6);

    const __nv_bfloat16* Ag = g_Abf + (size_t)(bm * BM) * KS;
    const __nv_bfloat16* Bg = g_Bbf + (size_t)(bn * BN) * KS;

    int lrow = tid >> 3;
    int lchk = tid & 7;

    #define LOADSTG(slot, k0) do {                                                   \
        uint32_t _sa = sbase + (uint32_t)(slot) * STG_BYTES;                         \
        uint32_t _sb = _sa + BM * BKB * 2;                                           \
        uint32_t _off = (uint32_t)(lrow * 128 + lchk * 16);                          \
        cp16(_sa + SWZ(_off), Ag + (size_t)lrow * KS + (k0) + lchk * 8);             \
        cp16(_sb + SWZ(_off), Bg + (size_t)lrow * KS + (k0) + lchk * 8);             \
        _Pragma("unroll")                                                            \
        for (int _j = 1; _j < 4; ++_j) {                                             \
            int _ch = tid + 256 * _j; int _r = _ch >> 3; int _c = _ch & 7;           \
            uint32_t _o = (uint32_t)(_r * 128 + _c * 16);                            \
            cp16(_sa + SWZ(_o), Ag + (size_t)_r * KS + (k0) + _c * 8);               \
            cp16(_sb + SWZ(_o), Bg + (size_t)_r * KS + (k0) + _c * 8);               \
        }                                                                            \
        CP_COMMIT();                                                                 \
    } while (0)

    float acc[4][4][4];
    #pragma unroll
    for (int i = 0; i < 4; ++i)
        #pragma unroll
        for (int j = 0; j < 4; ++j)
            #pragma unroll
            for (int q = 0; q < 4; ++q) acc[i][j][q] = 0.0f;

    LOADSTG(0, 0);
    LOADSTG(1, BKB);

    int arow = wm * 64 + (lane & 15);
    int aside = (lane >> 4) & 1;
    int brow = wn * 32 + (lane & 7);
    int bside = (lane >> 3) & 1;

    for (int i = 0; i < NK; ++i) {
        CP_WAIT1();
        __syncthreads();
        int slot = i % NSTG;
        uint32_t sa = sbase + (uint32_t)slot * STG_BYTES;
        uint32_t sb = sa + BM * BKB * 2;

        int nx = i + 2;
        if (nx < NK) LOADSTG(nx % NSTG, nx * BKB);
        else CP_COMMIT();

        #pragma unroll
        for (int ks = 0; ks < 4; ++ks) {
            uint32_t a[4][4], b[4][2];
            #pragma unroll
            for (int mt = 0; mt < 4; ++mt) {
                uint32_t off = (uint32_t)((arow + mt * 16) * 128 + ks * 32 + aside * 16);
                uint32_t ad = sa + SWZ(off);
                asm volatile("ldmatrix.sync.aligned.m8n8.x4.shared.b16 {%0,%1,%2,%3}, [%4];"
                    : "=r"(a[mt][0]), "=r"(a[mt][1]), "=r"(a[mt][2]), "=r"(a[mt][3]) : "r"(ad));
            }
            #pragma unroll
            for (int nt = 0; nt < 4; ++nt) {
                uint32_t off = (uint32_t)((brow + nt * 8) * 128 + ks * 32 + bside * 16);
                uint32_t bd = sb + SWZ(off);
                asm volatile("ldmatrix.sync.aligned.m8n8.x2.shared.b16 {%0,%1}, [%2];"
                    : "=r"(b[nt][0]), "=r"(b[nt][1]) : "r"(bd));
            }
            #pragma unroll
            for (int mt = 0; mt < 4; ++mt)
                #pragma unroll
                for (int nt = 0; nt < 4; ++nt) {
                    asm volatile(
                        "mma.sync.aligned.m16n8k16.row.col.f32.bf16.bf16.f32 "
                        "{%0,%1,%2,%3}, {%4,%5,%6,%7}, {%8,%9}, {%0,%1,%2,%3};"
                        : "+f"(acc[mt][nt][0]), "+f"(acc[mt][nt][1]),
                          "+f"(acc[mt][nt][2]), "+f"(acc[mt][nt][3])
                        : "r"(a[mt][0]), "r"(a[mt][1]), "r"(a[mt][2]), "r"(a[mt][3]),
                          "r"(b[nt][0]), "r"(b[nt][1]));
                }
        }
        __syncthreads();
    }

    #pragma unroll
    for (int mt = 0; mt < 4; ++mt) {
        int r0 = bm * BM + wm * 64 + mt * 16 + (lane >> 2);
        #pragma unroll
        for (int nt = 0; nt < 4; ++nt) {
            int col = bn * BN + wn * 32 + nt * 8 + 2 * (lane & 3);
            float2 bv = *(const float2*)&bias[col];
            float2 o0 = { acc[mt][nt][0] + bv.x, acc[mt][nt][1] + bv.y };
            float2 o1 = { acc[mt][nt][2] + bv.x, acc[mt][nt][3] + bv.y };
            *(__nv_bfloat162*)&g_Ebf[(size_t)r0 * LAT + col]       = __float22bfloat162_rn(o0);
            *(__nv_bfloat162*)&g_Ebf[(size_t)(r0 + 8) * LAT + col] = __float22bfloat162_rn(o1);
        }
    }
}

// ---------------- radix pass 0: top byte class (bf16 input) -----------------
#define RSEL_COLS 32
__global__ __launch_bounds__(256)
void k_radix0() {
    __shared__ unsigned int hist[256][RSEL_COLS + 1];
    int colbase = blockIdx.x * RSEL_COLS;
    int tx = threadIdx.x & (RSEL_COLS - 1);
    int ty = threadIdx.x / RSEL_COLS;
    for (int i = threadIdx.x; i < 256 * (RSEL_COLS + 1); i += 256)
        ((unsigned int*)hist)[i] = 0u;
    __syncthreads();

    int col = colbase + tx;
    for (int r = ty; r < BATCH; r += 8) {
        float v = __bfloat162float(g_Ebf[(size_t)r * LAT + col]);
        unsigned int u = f2ord(v);
        atomicAdd(&hist[u >> 24][tx], 1u);
    }
    __syncthreads();

    if (threadIdx.x < RSEL_COLS) {
        int kr = K_TOP;
        unsigned int cum = 0;
        int b = 255;
        for (; b >= 0; --b) {
            unsigned int h = hist[b][tx];
            cum += h;
            if ((int)cum >= kr) { kr -= (int)(cum - h); break; }
        }
        g_prefix[col] = (unsigned int)b << 24;
        g_krem[col]   = kr;
    }
}

// ---------------- radix pass 1 + bounds + collect + definite-in push --------
__global__ __launch_bounds__(256)
void k_radix1c() {
    __shared__ unsigned int hist[256][RSEL_COLS + 1];
    __shared__ float s_lo[RSEL_COLS], s_hi[RSEL_COLS];
    __shared__ int   s_def[RSEL_COLS];
    int colbase = blockIdx.x * RSEL_COLS;
    int tx = threadIdx.x & (RSEL_COLS - 1);
    int ty = threadIdx.x / RSEL_COLS;
    for (int i = threadIdx.x; i < 256 * (RSEL_COLS + 1); i += 256)
        ((unsigned int*)hist)[i] = 0u;
    __syncthreads();

    int col = colbase + tx;
    unsigned int pfx = g_prefix[col];
    for (int r = ty; r < BATCH; r += 8) {
        float v = __bfloat162float(g_Ebf[(size_t)r * LAT + col]);
        unsigned int u = f2ord(v);
        if ((u & 0xFF000000u) == pfx)
            atomicAdd(&hist[(u >> 16) & 255][tx], 1u);
    }
    __syncthreads();

    if (threadIdx.x < RSEL_COLS) {
        int kr = g_krem[col];
        unsigned int cum = 0;
        int b = 255;
        for (; b >= 0; --b) {
            unsigned int h = hist[b][tx];
            cum += h;
            if ((int)cum >= kr) { kr -= (int)(cum - h); break; }
        }
        unsigned int pfx2 = pfx | ((unsigned int)b << 16);
        s_lo[threadIdx.x] = ord2f(pfx2) - 2.0f * EPSB;
        s_hi[threadIdx.x] = ord2f(pfx2 | 0xFFFFu) + 2.0f * EPSB;
        s_def[threadIdx.x] = 0;
    }
    __syncthreads();

    // L2-hot rescan: definite-in -> push keep list; band -> candidates
    float lo = s_lo[tx], hi = s_hi[tx];
    int mydef = 0;
    for (int r = ty; r < BATCH; r += 8) {
        float v = __bfloat162float(g_Ebf[(size_t)r * LAT + col]);
        if (v > hi) {
            ++mydef;
            int s = atomicAdd(&g_rown[r], 1);
            if (s < ROW_CAP) g_rcols[(size_t)r * ROW_CAP + s] = col;
        } else if (v >= lo) {
            int p = atomicAdd(&g_candcnt[col], 1);
            if (p < CAND_CAP) g_candrow[(size_t)col * CAND_CAP + p] = r;
        }
    }
    if (mydef) atomicAdd(&s_def[tx], mydef);
    __syncthreads();
    if (threadIdx.x < RSEL_COLS)
        g_defcnt[col] = s_def[threadIdx.x];
}

// ---------------- exact fp32 dot + selection + keep-list push ---------------
// Sequential ascending-k fmaf chain: bit-identical to the R2 fp32 SGEMM whose
// selection passed (re-verified R12/R13/R15).
__global__ __launch_bounds__(128)
void k_exact(const float* __restrict__ X, const float* __restrict__ W,
             const float* __restrict__ eb) {
    int col = blockIdx.x;
    int nc = g_candcnt[col]; if (nc > CAND_CAP) nc = CAND_CAP;
    int ci = threadIdx.x;
    if (ci < nc) {
        int row = g_candrow[(size_t)col * CAND_CAP + ci];
        const float* x = X + (size_t)row * IN_DIM;
        const float* w = W + (size_t)col * IN_DIM;
        float s = 0.0f;
        for (int k = 0; k < IN_DIM; k += 4) {
            float4 xv = *(const float4*)&x[k];
            float4 wv = *(const float4*)&w[k];
            s = fmaf(xv.x, wv.x, s);
            s = fmaf(xv.y, wv.y, s);
            s = fmaf(xv.z, wv.z, s);
            s = fmaf(xv.w, wv.w, s);
        }
        g_candval[(size_t)col * CAND_CAP + ci] = s + eb[col];
    }
    __syncthreads();
    if (threadIdx.x == 0) {
        int need = K_TOP - g_defcnt[col];
        if (need < 0) need = 0;
        if (need > nc) need = nc;
        int*   cr = &g_candrow[(size_t)col * CAND_CAP];
        float* cv = &g_candval[(size_t)col * CAND_CAP];
        for (int i = 0; i < need; ++i) {
            int best = i;
            unsigned int bo = f2ord(cv[best]);
            for (int j = i + 1; j < nc; ++j) {
                unsigned int jo = f2ord(cv[j]);
                if (jo > bo || (jo == bo && cr[j] < cr[best])) { best = j; bo = jo; }
            }
            if (best != i) {
                int tr = cr[i]; cr[i] = cr[best]; cr[best] = tr;
                float tv = cv[i]; cv[i] = cv[best]; cv[best] = tv;
            }
            int row = cr[i];
            int s = atomicAdd(&g_rown[row], 1);
            if (s < ROW_CAP) g_rcols[(size_t)row * ROW_CAP + s] = col;
        }
    }
}

// ---------------- fused exact repair + decode -------------------------------
// Phase 1: exact fp32 value per kept col (warp/col), scatter into E + smem.
// Phase 2: decoder accumulation over kept cols (threads over IN_DIM).
__global__ __launch_bounds__(256)
void k_rd(const float* __restrict__ X, const float* __restrict__ W,
          const float* __restrict__ eb, const float* __restrict__ db,
          float* __restrict__ E, float* __restrict__ out) {
    __shared__ float xs[IN_DIM];
    __shared__ float vals[ROW_CAP_S];
    __shared__ int   cols_s[ROW_CAP_S];
    int b = blockIdx.x;
    for (int i = threadIdx.x; i < IN_DIM; i += 256)
        xs[i] = X[(size_t)b * IN_DIM + i];
    int n = g_rown[b]; if (n > ROW_CAP_S) n = ROW_CAP_S;
    for (int i = threadIdx.x; i < n; i += 256)
        cols_s[i] = g_rcols[(size_t)b * ROW_CAP + i];
    __syncthreads();

    int warp = threadIdx.x >> 5;
    int lane = threadIdx.x & 31;
    for (int e = warp; e < n; e += 8) {
        int col = cols_s[e];
        const float* w = W + (size_t)col * IN_DIM;
        float s = 0.0f;
        #pragma unroll 4
        for (int k = lane; k < IN_DIM; k += 32)
            s = fmaf(xs[k], w[k], s);
        #pragma unroll
        for (int o = 16; o > 0; o >>= 1)
            s += __shfl_xor_sync(0xFFFFFFFFu, s, o);
        if (lane == 0) {
            float v = s + eb[col];
            vals[e] = v;
            E[(size_t)b * LAT + col] = v;
        }
    }
    __syncthreads();

    int t = threadIdx.x;
    float acc0 = db[t], acc1 = db[t + 256], acc2 = db[t + 512];
    for (int e = 0; e < n; ++e) {
        float v = vals[e];
        const float* w = &g_dwt[(size_t)cols_s[e] * IN_DIM];
        acc0 += v * w[t];
        acc1 += v * w[t + 256];
        acc2 += v * w[t + 512];
    }
    out[(size_t)b * IN_DIM + t]       = acc0;
    out[(size_t)b * IN_DIM + t + 256] = acc1;
    out[(size_t)b * IN_DIM + t + 512] = acc2;
}

// ---------------- launch ----------------
extern "C" void kernel_launch(void* const* d_in, const int* in_sizes, int n_in,
                              void* d_out, int out_size) {
    const float* x     = (const float*)d_in[0];
    const float* enc_w = (const float*)d_in[1];
    const float* enc_b = (const float*)d_in[2];
    const float* dec_w = (const float*)d_in[3];
    const float* dec_b = (const float*)d_in[4];

    float* dec_out = (float*)d_out;
    float* sp      = dec_out + (size_t)BATCH * IN_DIM;

    cudaFuncSetAttribute(k_hmma, cudaFuncAttributeMaxDynamicSharedMemorySize, SMEM_GEMM);

    k_init<<<LAT / 256, 256>>>();
    cudaMemsetAsync(sp, 0, (size_t)BATCH * LAT * sizeof(float));
    k_cvtA<<<(BATCH * IN_DIM / 2) / 256, 256>>>(x);
    k_cvtB<<<(LAT * IN_DIM / 2) / 256, 256>>>(enc_w);
    k_transpose<<<dim3(LAT / 32, IN_DIM / 32), dim3(32, 8)>>>(dec_w);

    k_hmma<<<(BATCH / BM) * (LAT / BN), 256, SMEM_GEMM>>>(enc_b);

    k_radix0<<<LAT / RSEL_COLS, 256>>>();
    k_radix1c<<<LAT / RSEL_COLS, 256>>>();
    k_exact<<<LAT, 128>>>(x, enc_w, enc_b);
    k_rd<<<BATCH, 256>>>(x, enc_w, enc_b, dec_b, sp, dec_out);
}